// round 7
// baseline (speedup 1.0000x reference)
#include <cuda_runtime.h>
#include <cuda_bf16.h>
#include <cstdint>

#define NCLS 54
#define RPB  128
#define THREADS 128

// -log(1 - 53*0.001) = -log(0.947)
#define C0_TERM  0.05445614f
#define LOG2E    1.44269504f

__device__ double g_acc;           // module-load zeroed; reset by last block each run
__device__ unsigned int g_done;

__device__ __forceinline__ uint32_t smem_u32(const void* p) {
    return (uint32_t)__cvta_generic_to_shared(p);
}

__global__ void __launch_bounds__(THREADS, 8)
importance_loss_tma(const float* __restrict__ logits,
                    const int*   __restrict__ target,
                    const int*   __restrict__ mask,    // bool promoted to int32
                    float* __restrict__ out,
                    int batch, int nblocks)
{
    __shared__ float s[RPB * NCLS];                    // 27648 B -> 8 CTAs/SM
    __shared__ unsigned char smask[64];
    __shared__ float red[THREADS / 32];
    __shared__ __align__(8) unsigned long long mbar;

    const int tid  = threadIdx.x;
    const int row0 = blockIdx.x * RPB;
    const int rows = min(RPB, batch - row0);
    const int nbytes = rows * NCLS * 4;
    const int nmain  = nbytes & ~15;                   // bulk copy: 16B multiple

    if (tid == 0)
        asm volatile("mbarrier.init.shared.b64 [%0], 1;"
                     :: "r"(smem_u32(&mbar)) : "memory");
    __syncthreads();

    const char* src = (const char*)(logits + (long long)row0 * NCLS); // 27648*blk -> 16B aligned
    if (tid == 0) {
        asm volatile("mbarrier.arrive.expect_tx.shared.b64 _, [%0], %1;"
                     :: "r"(smem_u32(&mbar)), "r"((uint32_t)nmain) : "memory");
        asm volatile("cp.async.bulk.shared::cta.global.mbarrier::complete_tx::bytes "
                     "[%0], [%1], %2, [%3];"
                     :: "r"(smem_u32(s)), "l"(src), "r"((uint32_t)nmain),
                        "r"(smem_u32(&mbar)) : "memory");
        for (int b = nmain; b < nbytes; b += 4)        // <16B tail (unused for this shape)
            *(float*)((char*)s + b) = *(const float*)(src + b);
    }
    if (tid < NCLS) smask[tid] = (unsigned char)(mask[tid] != 0);

    // overlap target load with the TMA copy
    int t = 0;
    if (tid < rows) t = target[row0 + tid];

    // wait for bulk copy (phase 0), acquire semantics
    {
        uint32_t mba = smem_u32(&mbar);
        uint32_t done;
        asm volatile("{\n\t.reg .pred p;\n\t"
                     "mbarrier.try_wait.parity.acquire.cta.shared::cta.b64 p, [%1], 0;\n\t"
                     "selp.b32 %0, 1, 0, p;\n\t}"
                     : "=r"(done) : "r"(mba) : "memory");
        if (!done) {
            asm volatile("{\n\t.reg .pred P1;\n\t"
                         "WL_%=:\n\t"
                         "mbarrier.try_wait.parity.acquire.cta.shared::cta.b64 P1, [%0], 0, 0x989680;\n\t"
                         "@P1 bra.uni WD_%=;\n\t"
                         "bra.uni WL_%=;\n\t"
                         "WD_%=:\n\t}"
                         :: "r"(mba) : "memory");
        }
    }
    __syncthreads();   // covers t0's tail + smask stores for all threads

    // ---- one row per thread; conflict-free LDS.64, two passes ----
    float term = 0.0f;
    if (tid < rows) {
        const float2* x2 = (const float2*)(s + tid * NCLS);  // 216B stride, 8B aligned

        // pass 1: max via 4 independent fmaxf chains
        float m0 = -3.0e38f, m1 = -3.0e38f, m2 = -3.0e38f, m3 = -3.0e38f;
        #pragma unroll
        for (int k = 0; k < NCLS / 2; k++) {
            float2 v = x2[k];
            if (k & 1) { m2 = fmaxf(m2, v.x); m3 = fmaxf(m3, v.y); }
            else       { m0 = fmaxf(m0, v.x); m1 = fmaxf(m1, v.y); }
        }
        const float m  = fmaxf(fmaxf(m0, m1), fmaxf(m2, m3));
        const float mh = m * LOG2E;

        // pass 2 (reverse order): exp2-sum with FFMA arg + argmax via predicated mov.
        // Descending k, checking .y before .x, leaves the SMALLEST matching index
        // in am => first occurrence, matching jnp.argmax.
        float s0 = 0.f, s1 = 0.f, s2 = 0.f, s3 = 0.f;
        int am = 0;
        #pragma unroll
        for (int k = NCLS / 2 - 1; k >= 0; k--) {
            float2 v = x2[k];
            float e0 = exp2f(__fmaf_rn(v.x, LOG2E, -mh));
            float e1 = exp2f(__fmaf_rn(v.y, LOG2E, -mh));
            if (k & 1) { s2 += e0; s3 += e1; }
            else       { s0 += e0; s1 += e1; }
            if (v.y == m) am = 2 * k + 1;
            if (v.x == m) am = 2 * k;
        }
        const float sum = (s0 + s1) + (s2 + s3);

        const float xt  = s[tid * NCLS + t];
        const bool keep = (smask[am] | smask[t]) != 0;
        term = keep ? (m + __logf(sum) - xt) : C0_TERM;
    }

    // ---- block reduction ----
    #pragma unroll
    for (int o = 16; o > 0; o >>= 1)
        term += __shfl_down_sync(0xffffffffu, term, o);
    const int lane = tid & 31;
    const int w    = tid >> 5;
    if (lane == 0) red[w] = term;
    __syncthreads();

    if (tid == 0) {
        float bs = 0.0f;
        #pragma unroll
        for (int i = 0; i < THREADS / 32; i++) bs += red[i];
        atomicAdd(&g_acc, (double)bs);
        __threadfence();
        unsigned int done = atomicAdd(&g_done, 1u);
        if (done == (unsigned int)(nblocks - 1)) {
            double total = atomicAdd(&g_acc, 0.0);     // atomic read via L2
            out[0] = (float)(total / (double)batch);
            g_acc  = 0.0;                              // reset for next graph replay
            g_done = 0u;
        }
    }
}

extern "C" void kernel_launch(void* const* d_in, const int* in_sizes, int n_in,
                              void* d_out, int out_size)
{
    const float* logits = (const float*)d_in[0];
    const int*   target = (const int*)d_in[1];
    const int*   mask   = (const int*)d_in[2];
    float* out = (float*)d_out;

    const int batch  = in_sizes[1];
    const int blocks = (batch + RPB - 1) / RPB;

    importance_loss_tma<<<blocks, THREADS>>>(logits, target, mask, out, batch, blocks);
}

// round 8
// speedup vs baseline: 1.2377x; 1.2377x over previous
#include <cuda_runtime.h>
#include <cuda_bf16.h>
#include <cstdint>

#define NCLS    54
#define TILE    128
#define THREADS 128
#define TILE_FLOATS (TILE * NCLS)
#define TILE_BYTES  (TILE_FLOATS * 4)      // 27648
#define CTAS_PER_SM 4

// -log(1 - 53*0.001) = -log(0.947)
#define C0_TERM  0.05445614f
#define LOG2E    1.44269504f

__device__ double g_acc;            // module-load zeroed; reset by last block each run
__device__ unsigned int g_done;

__device__ __forceinline__ uint32_t smem_u32(const void* p) {
    return (uint32_t)__cvta_generic_to_shared(p);
}

__device__ __forceinline__ void mbar_wait(uint32_t mba, int phase) {
    uint32_t done;
    asm volatile("{\n\t.reg .pred p;\n\t"
                 "mbarrier.try_wait.parity.acquire.cta.shared::cta.b64 p, [%1], %2;\n\t"
                 "selp.b32 %0, 1, 0, p;\n\t}"
                 : "=r"(done) : "r"(mba), "r"((uint32_t)phase) : "memory");
    if (!done) {
        asm volatile("{\n\t.reg .pred P1;\n\t"
                     "WL_%=:\n\t"
                     "mbarrier.try_wait.parity.acquire.cta.shared::cta.b64 P1, [%0], %1, 0x989680;\n\t"
                     "@P1 bra.uni WD_%=;\n\t"
                     "bra.uni WL_%=;\n\t"
                     "WD_%=:\n\t}"
                     :: "r"(mba), "r"((uint32_t)phase) : "memory");
    }
}

// issue bulk copy of one tile into buf, completion on bar
__device__ __forceinline__ void issue_tile(const float* __restrict__ logits,
                                           int tile, int batch,
                                           float* buf, uint32_t bar) {
    const int row0  = tile * TILE;
    const int rows  = min(TILE, batch - row0);
    const uint32_t nmain = (uint32_t)(rows * NCLS * 4) & ~15u;
    const char* src = (const char*)(logits + (long long)row0 * NCLS);
    asm volatile("mbarrier.arrive.expect_tx.shared.b64 _, [%0], %1;"
                 :: "r"(bar), "r"(nmain) : "memory");
    asm volatile("cp.async.bulk.shared::cta.global.mbarrier::complete_tx::bytes "
                 "[%0], [%1], %2, [%3];"
                 :: "r"(smem_u32(buf)), "l"(src), "r"(nmain), "r"(bar) : "memory");
}

// softmax row math from a row pointer (hot path: pointer is shared-derived -> LDS)
__device__ __forceinline__ float row_term(const float* __restrict__ row, int t,
                                          const unsigned char* __restrict__ smask) {
    const float2* x2 = (const float2*)row;          // 216B stride, 8B aligned, conflict-free
    float m0 = -3.0e38f, m1 = -3.0e38f, m2 = -3.0e38f, m3 = -3.0e38f;
    #pragma unroll
    for (int k = 0; k < NCLS / 2; k++) {
        float2 v = x2[k];
        if (k & 1) { m2 = fmaxf(m2, v.x); m3 = fmaxf(m3, v.y); }
        else       { m0 = fmaxf(m0, v.x); m1 = fmaxf(m1, v.y); }
    }
    const float m  = fmaxf(fmaxf(m0, m1), fmaxf(m2, m3));
    const float mh = m * LOG2E;

    // reverse order: leaves the SMALLEST matching index (first occurrence, jnp.argmax)
    float s0 = 0.f, s1 = 0.f, s2 = 0.f, s3 = 0.f;
    int am = 0;
    #pragma unroll
    for (int k = NCLS / 2 - 1; k >= 0; k--) {
        float2 v = x2[k];
        float e0 = exp2f(__fmaf_rn(v.x, LOG2E, -mh));
        float e1 = exp2f(__fmaf_rn(v.y, LOG2E, -mh));
        if (k & 1) { s2 += e0; s3 += e1; }
        else       { s0 += e0; s1 += e1; }
        if (v.y == m) am = 2 * k + 1;
        if (v.x == m) am = 2 * k;
    }
    const float sum = (s0 + s1) + (s2 + s3);
    const float xt  = row[t];
    const bool keep = (smask[am] | smask[t]) != 0;
    return keep ? (m + __logf(sum) - xt) : C0_TERM;
}

__global__ void __launch_bounds__(THREADS, CTAS_PER_SM)
importance_loss_persist(const float* __restrict__ logits,
                        const int*   __restrict__ target,
                        const int*   __restrict__ mask,   // bool promoted to int32
                        float* __restrict__ out,
                        int batch)
{
    extern __shared__ __align__(16) float buf[];          // 2 * TILE_FLOATS
    __shared__ unsigned char smask[64];
    __shared__ float red[THREADS / 32];
    __shared__ __align__(8) unsigned long long mbar[2];

    const int tid     = threadIdx.x;
    const int ntiles  = (batch + TILE - 1) / TILE;
    const int stride  = gridDim.x;

    if (tid < 2)
        asm volatile("mbarrier.init.shared.b64 [%0], 1;"
                     :: "r"(smem_u32(&mbar[tid])) : "memory");
    if (tid < NCLS) smask[tid] = (unsigned char)(mask[tid] != 0);
    __syncthreads();

    const uint32_t bar0 = smem_u32(&mbar[0]);
    const uint32_t bar1 = smem_u32(&mbar[1]);

    int tile = blockIdx.x;
    if (tid == 0 && tile < ntiles)
        issue_tile(logits, tile, batch, buf, bar0);

    float acc = 0.0f;
    int parity = 0, phA = 0, phB = 0;

    for (; tile < ntiles; tile += stride) {
        const int nextt = tile + stride;
        float*   cbuf = parity ? (buf + TILE_FLOATS) : buf;
        float*   obuf = parity ? buf : (buf + TILE_FLOATS);
        const uint32_t cbar = parity ? bar1 : bar0;
        const uint32_t obar = parity ? bar0 : bar1;

        // keep the DRAM stream busy: queue next tile before consuming current
        if (tid == 0 && nextt < ntiles)
            issue_tile(logits, nextt, batch, obuf, obar);

        const int row0 = tile * TILE;
        const int rows = min(TILE, batch - row0);
        int t = 0;
        if (tid < rows) t = target[row0 + tid];           // overlaps with TMA

        const int ph = parity ? phB : phA;
        mbar_wait(cbar, ph);
        if (parity) phB ^= 1; else phA ^= 1;

        if (tid < rows) {
            const int full_rows = ((rows * NCLS * 4) & ~15) / (NCLS * 4);
            if (tid < full_rows) {                        // hot path: LDS
                acc += row_term(cbuf + tid * NCLS, t, smask);
            } else {                                      // cold path (never for 2M%128==0)
                acc += row_term(logits + (long long)(row0 + tid) * NCLS, t, smask);
            }
        }
        __syncthreads();                                  // release cbuf for re-fill
        parity ^= 1;
    }

    // ---- final block reduction (once per CTA) ----
    #pragma unroll
    for (int o = 16; o > 0; o >>= 1)
        acc += __shfl_down_sync(0xffffffffu, acc, o);
    const int lane = tid & 31, w = tid >> 5;
    if (lane == 0) red[w] = acc;
    __syncthreads();

    if (tid == 0) {
        float bs = 0.0f;
        #pragma unroll
        for (int i = 0; i < THREADS / 32; i++) bs += red[i];
        atomicAdd(&g_acc, (double)bs);
        __threadfence();
        unsigned int done = atomicAdd(&g_done, 1u);
        if (done == gridDim.x - 1) {
            double total = atomicAdd(&g_acc, 0.0);        // atomic read via L2
            out[0] = (float)(total / (double)batch);
            g_acc  = 0.0;                                 // reset for next graph replay
            g_done = 0u;
        }
    }
}

extern "C" void kernel_launch(void* const* d_in, const int* in_sizes, int n_in,
                              void* d_out, int out_size)
{
    const float* logits = (const float*)d_in[0];
    const int*   target = (const int*)d_in[1];
    const int*   mask   = (const int*)d_in[2];
    float* out = (float*)d_out;

    const int batch = in_sizes[1];

    static int grid = 0;
    if (grid == 0) {
        int dev = 0, sms = 148;
        cudaGetDevice(&dev);
        cudaDeviceGetAttribute(&sms, cudaDevAttrMultiProcessorCount, dev);
        cudaFuncSetAttribute(importance_loss_persist,
                             cudaFuncAttributeMaxDynamicSharedMemorySize,
                             2 * TILE_BYTES);
        grid = sms * CTAS_PER_SM;
    }

    importance_loss_persist<<<grid, THREADS, 2 * TILE_BYTES>>>(logits, target, mask, out, batch);
}